// round 17
// baseline (speedup 1.0000x reference)
#include <cuda_runtime.h>
#include <cuda_bf16.h>
#include <cuda_fp16.h>
#include <stdint.h>

#define N_NODES 50000
#define N_EDGES 1000000
#define IN_SIZE 256
#define OUT_SIZE 128
#define N_ET 3
#define N_TOT (N_ET * N_NODES)          // 150000
#define TOTAL_E (N_ET * N_EDGES)        // 3000000
#define HALF_E (TOTAL_E / 2)            // 1500000
#define SCAN_CHUNK 2048
#define SCAN_BLOCKS ((N_TOT + SCAN_CHUNK - 1) / SCAN_CHUNK)   // 74
#define GEMM_BX ((N_NODES + 127) / 128) // 391

// Scratch: Wh in fp16 (38.4MB), kept L2-resident via evict_last cache hints
__device__ __half g_Wh[(size_t)N_ET * N_NODES * OUT_SIZE];
__device__ int   g_cnt[N_TOT];          // zeroed by scan_a after use -> stays zero
__device__ int   g_off[N_TOT + 1];
__device__ int   g_pos[N_TOT];
__device__ int   g_part[SCAN_BLOCKS];
__device__ int   g_eidx[TOTAL_E];       // src node per edge, dst-sorted

// ---------------------------------------------------------------------------
// Cache-policy helpers (createpolicy + cache_hint form: valid for all widths)
// ---------------------------------------------------------------------------
__device__ __forceinline__ uint64_t pol_evict_last() {
    uint64_t p;
    asm("createpolicy.fractional.L2::evict_last.b64 %0, 1.0;" : "=l"(p));
    return p;
}
__device__ __forceinline__ uint64_t pol_evict_first() {
    uint64_t p;
    asm("createpolicy.fractional.L2::evict_first.b64 %0, 1.0;" : "=l"(p));
    return p;
}
__device__ __forceinline__ float4 ldg_evf_f4(const float* p, uint64_t pol) {
    float4 r;
    asm volatile("ld.global.nc.L2::cache_hint.v4.f32 {%0,%1,%2,%3}, [%4], %5;"
                 : "=f"(r.x), "=f"(r.y), "=f"(r.z), "=f"(r.w) : "l"(p), "l"(pol));
    return r;
}
__device__ __forceinline__ int4 ldg_evf_i4(const int* p, uint64_t pol) {
    int4 r;
    asm volatile("ld.global.nc.L2::cache_hint.v4.s32 {%0,%1,%2,%3}, [%4], %5;"
                 : "=r"(r.x), "=r"(r.y), "=r"(r.z), "=r"(r.w) : "l"(p), "l"(pol));
    return r;
}
__device__ __forceinline__ uint2 ldg_evl_u2(const __half* p, uint64_t pol) {
    uint2 r;
    asm volatile("ld.global.nc.L2::cache_hint.v2.u32 {%0,%1}, [%2], %3;"
                 : "=r"(r.x), "=r"(r.y) : "l"(p), "l"(pol));
    return r;
}
__device__ __forceinline__ void stg_evl_u32(__half* p, uint32_t v, uint64_t pol) {
    asm volatile("st.global.L2::cache_hint.u32 [%0], %1, %2;"
                 :: "l"(p), "r"(v), "l"(pol) : "memory");
}

// ---------------------------------------------------------------------------
// CSR build (round-14: split hist across streams)
// ---------------------------------------------------------------------------
__global__ void hist_kernel(const int* __restrict__ edst, int e_begin, int e_end) {
    int base = e_begin + (blockIdx.x * blockDim.x + threadIdx.x) * 4;
    if (base >= e_end) return;
    uint64_t pf = pol_evict_first();
    int4 d4 = ldg_evf_i4(&edst[base], pf);
    int et0 = base / N_EDGES;
    int et3 = (base + 3) / N_EDGES;
    if (et0 == et3) {
        int o = et0 * N_NODES;
        atomicAdd(&g_cnt[o + d4.x], 1);
        atomicAdd(&g_cnt[o + d4.y], 1);
        atomicAdd(&g_cnt[o + d4.z], 1);
        atomicAdd(&g_cnt[o + d4.w], 1);
    } else {
        atomicAdd(&g_cnt[((base + 0) / N_EDGES) * N_NODES + d4.x], 1);
        atomicAdd(&g_cnt[((base + 1) / N_EDGES) * N_NODES + d4.y], 1);
        atomicAdd(&g_cnt[((base + 2) / N_EDGES) * N_NODES + d4.z], 1);
        atomicAdd(&g_cnt[((base + 3) / N_EDGES) * N_NODES + d4.w], 1);
    }
}

__global__ __launch_bounds__(256) void scan_a_kernel() {
    __shared__ int s[256];
    const int tid = threadIdx.x;
    const int base = blockIdx.x * SCAN_CHUNK + tid * 8;
    int v[8];
    int tsum = 0;
#pragma unroll
    for (int k = 0; k < 8; k++) {
        int i = base + k;
        v[k] = (i < N_TOT) ? g_cnt[i] : 0;
        if (i < N_TOT) g_cnt[i] = 0;        // leave zeroed for next replay
        tsum += v[k];
    }
    s[tid] = tsum;
    __syncthreads();
    for (int off = 1; off < 256; off <<= 1) {
        int t = (tid >= off) ? s[tid - off] : 0;
        __syncthreads();
        s[tid] += t;
        __syncthreads();
    }
    int run = s[tid] - tsum;
#pragma unroll
    for (int k = 0; k < 8; k++) {
        int i = base + k;
        if (i < N_TOT) g_off[i] = run;
        run += v[k];
    }
    if (tid == 255) g_part[blockIdx.x] = s[255];
}

__global__ __launch_bounds__(128) void scan_b_kernel() {
    __shared__ int s[128];
    int tid = threadIdx.x;
    int v = (tid < SCAN_BLOCKS) ? g_part[tid] : 0;
    s[tid] = v;
    __syncthreads();
    for (int off = 1; off < 128; off <<= 1) {
        int t = (tid >= off) ? s[tid - off] : 0;
        __syncthreads();
        s[tid] += t;
        __syncthreads();
    }
    if (tid < SCAN_BLOCKS) g_part[tid] = s[tid] - v;   // exclusive
    if (tid == 127) g_off[N_TOT] = s[127];
}

__global__ void scan_c_kernel() {
    int i = blockIdx.x * blockDim.x + threadIdx.x;
    if (i >= N_TOT) return;
    int o = g_off[i] + g_part[i / SCAN_CHUNK];
    g_off[i] = o;
    g_pos[i] = o;
}

__global__ void fill_kernel(const int* __restrict__ esrc,
                            const int* __restrict__ edst) {
    int base = (blockIdx.x * blockDim.x + threadIdx.x) * 4;
#pragma unroll
    for (int k = 0; k < 4; k++) {
        int i = base + k;
        if (i < TOTAL_E) {
            int et = i / N_EDGES;
            int d = __ldg(&edst[i]);
            int s = __ldg(&esrc[i]);
            int p = atomicAdd(&g_pos[et * N_NODES + d], 1);
            g_eidx[p] = s;
        }
    }
}

// ---------------------------------------------------------------------------
// bf16-split GEMM helpers
// ---------------------------------------------------------------------------
#define MMA_BF16(D, A, B)                                                     \
    asm volatile(                                                             \
        "mma.sync.aligned.m16n8k16.row.col.f32.bf16.bf16.f32 "                \
        "{%0,%1,%2,%3}, {%4,%5,%6,%7}, {%8,%9}, {%0,%1,%2,%3};"               \
        : "+f"(D[0]), "+f"(D[1]), "+f"(D[2]), "+f"(D[3])                      \
        : "r"(A[0]), "r"(A[1]), "r"(A[2]), "r"(A[3]), "r"(B[0]), "r"(B[1]))

__device__ __forceinline__ void bf16_split2(float a, float b,
                                            uint32_t& hi, uint32_t& lo) {
    __nv_bfloat162 h, l;
    h.x = __float2bfloat16(a);
    h.y = __float2bfloat16(b);
    l.x = __float2bfloat16(a - __bfloat162float(h.x));
    l.y = __float2bfloat16(b - __bfloat162float(h.y));
    hi = *(uint32_t*)&h;
    lo = *(uint32_t*)&l;
}

#define PS 12   // pair-stride: 8 k-pairs + 4 pad

// ---------------------------------------------------------------------------
// Per-etype GEMM: Wh[et] = x @ W[et], split-bf16 (3x m16n8k16 per k-tile).
// x streamed with evict_first; Wh written with evict_last (stays for gathers).
// ---------------------------------------------------------------------------
__global__ __launch_bounds__(256, 2) void gemm_kernel(const float* __restrict__ x,
                                                      const float* __restrict__ W,
                                                      int et) {
    const int m0 = blockIdx.x * 128;
    const int tid = threadIdx.x;
    const int wid = tid >> 5;
    const int lane = tid & 31;
    const int m_off = (wid >> 1) * 32;
    const int n_off = (wid & 1) * 64;
    const int gq = lane >> 2;
    const int tg = lane & 3;

    __shared__ uint32_t Ah[128 * PS];
    __shared__ uint32_t Al[128 * PS];
    __shared__ uint32_t Bh[128 * PS];
    __shared__ uint32_t Bl[128 * PS];

    const float* Wt = W + (size_t)et * IN_SIZE * OUT_SIZE;
    const uint64_t pf = pol_evict_first();
    const uint64_t pl = pol_evict_last();

    float acc[2][8][4];
#pragma unroll
    for (int i = 0; i < 2; i++)
#pragma unroll
        for (int j = 0; j < 8; j++)
#pragma unroll
            for (int c = 0; c < 4; c++) acc[i][j][c] = 0.0f;

    const int wn = tid & 127;
    const int wkh = tid >> 7;

    for (int k0 = 0; k0 < IN_SIZE; k0 += 16) {
#pragma unroll
        for (int i = 0; i < 2; i++) {
            int f4 = tid + i * 256;
            int row = f4 >> 2;
            int kc = (f4 & 3) * 4;
            int gm = m0 + row;
            float4 v = make_float4(0.f, 0.f, 0.f, 0.f);
            if (gm < N_NODES) v = ldg_evf_f4(&x[(size_t)gm * IN_SIZE + k0 + kc], pf);
            uint32_t h0, l0, h1, l1;
            bf16_split2(v.x, v.y, h0, l0);
            bf16_split2(v.z, v.w, h1, l1);
            int p = row * PS + (kc >> 1);
            Ah[p] = h0; Ah[p + 1] = h1;
            Al[p] = l0; Al[p + 1] = l1;
        }
        {
            float w[8];
#pragma unroll
            for (int i = 0; i < 8; i++)
                w[i] = __ldg(&Wt[(size_t)(k0 + wkh * 8 + i) * OUT_SIZE + wn]);
            int p = wn * PS + wkh * 4;
#pragma unroll
            for (int q = 0; q < 4; q++) {
                uint32_t h, l;
                bf16_split2(w[2 * q], w[2 * q + 1], h, l);
                Bh[p + q] = h;
                Bl[p + q] = l;
            }
        }
        __syncthreads();

        uint32_t ahi[2][4], alo[2][4];
#pragma unroll
        for (int mf = 0; mf < 2; mf++) {
            int r = (m_off + mf * 16 + gq) * PS;
            ahi[mf][0] = Ah[r + tg];
            ahi[mf][1] = Ah[r + 8 * PS + tg];
            ahi[mf][2] = Ah[r + 4 + tg];
            ahi[mf][3] = Ah[r + 8 * PS + 4 + tg];
            alo[mf][0] = Al[r + tg];
            alo[mf][1] = Al[r + 8 * PS + tg];
            alo[mf][2] = Al[r + 4 + tg];
            alo[mf][3] = Al[r + 8 * PS + 4 + tg];
        }
#pragma unroll
        for (int nf = 0; nf < 8; nf++) {
            int n = (n_off + nf * 8 + gq) * PS;
            uint32_t bhi[2], blo[2];
            bhi[0] = Bh[n + tg];
            bhi[1] = Bh[n + 4 + tg];
            blo[0] = Bl[n + tg];
            blo[1] = Bl[n + 4 + tg];
#pragma unroll
            for (int mf = 0; mf < 2; mf++) {
                MMA_BF16(acc[mf][nf], ahi[mf], bhi);
                MMA_BF16(acc[mf][nf], ahi[mf], blo);
                MMA_BF16(acc[mf][nf], alo[mf], bhi);
            }
        }
        __syncthreads();
    }

    __half* dst = g_Wh + (size_t)et * N_NODES * OUT_SIZE;
#pragma unroll
    for (int mf = 0; mf < 2; mf++) {
#pragma unroll
        for (int nf = 0; nf < 8; nf++) {
            int row = m0 + m_off + mf * 16 + gq;
            int col = n_off + nf * 8 + tg * 2;
            if (row < N_NODES) {
                __half2 h = __floats2half2_rn(acc[mf][nf][0], acc[mf][nf][1]);
                stg_evl_u32(&dst[(size_t)row * OUT_SIZE + col], *(uint32_t*)&h, pl);
            }
            if (row + 8 < N_NODES) {
                __half2 h = __floats2half2_rn(acc[mf][nf][2], acc[mf][nf][3]);
                stg_evl_u32(&dst[(size_t)(row + 8) * OUT_SIZE + col], *(uint32_t*)&h, pl);
            }
        }
    }
}

// ---------------------------------------------------------------------------
// Per-etype gather + mean + bias: 16-deep MLP, then 8, then 1.
// Wh loads use evict_last (rows re-read ~20x within the gather).
// ---------------------------------------------------------------------------
__global__ __launch_bounds__(256) void gather_kernel(float* __restrict__ out,
                                                     const float* __restrict__ b,
                                                     int et) {
    const int wid = threadIdx.x >> 5;
    const int lane = threadIdx.x & 31;
    const int n = blockIdx.x * 8 + wid;
    if (n >= N_NODES) return;

    const int base = et * N_NODES + n;
    const int beg = __ldg(&g_off[base]);
    const int end = __ldg(&g_off[base + 1]);

    const __half* wh = g_Wh + (size_t)et * N_NODES * OUT_SIZE;
    const uint64_t pl = pol_evict_last();
    float4 a0 = make_float4(0.f, 0.f, 0.f, 0.f);
    float4 a1 = make_float4(0.f, 0.f, 0.f, 0.f);

#define ACC(A, U)                                                            \
    {                                                                        \
        float2 f0 = __half22float2(*(const __half2*)&U.x);                   \
        float2 f1 = __half22float2(*(const __half2*)&U.y);                   \
        A.x += f0.x; A.y += f0.y; A.z += f1.x; A.w += f1.y;                  \
    }

    int j = beg;
    for (; j + 16 <= end; j += 16) {
        int s[16];
#pragma unroll
        for (int k = 0; k < 16; k++) s[k] = __ldg(&g_eidx[j + k]);
        uint2 u[16];
#pragma unroll
        for (int k = 0; k < 16; k++)
            u[k] = ldg_evl_u2(&wh[(size_t)s[k] * OUT_SIZE + lane * 4], pl);
#pragma unroll
        for (int k = 0; k < 8; k++) ACC(a0, u[k])
#pragma unroll
        for (int k = 8; k < 16; k++) ACC(a1, u[k])
    }
    for (; j + 8 <= end; j += 8) {
        int s[8];
#pragma unroll
        for (int k = 0; k < 8; k++) s[k] = __ldg(&g_eidx[j + k]);
        uint2 u[8];
#pragma unroll
        for (int k = 0; k < 8; k++)
            u[k] = ldg_evl_u2(&wh[(size_t)s[k] * OUT_SIZE + lane * 4], pl);
#pragma unroll
        for (int k = 0; k < 4; k++) ACC(a0, u[k])
#pragma unroll
        for (int k = 4; k < 8; k++) ACC(a1, u[k])
    }
    for (; j < end; j++) {
        int s = __ldg(&g_eidx[j]);
        uint2 u = ldg_evl_u2(&wh[(size_t)s * OUT_SIZE + lane * 4], pl);
        ACC(a0, u)
    }
#undef ACC
    a0.x += a1.x; a0.y += a1.y; a0.z += a1.z; a0.w += a1.w;

    float4 r;
    int cnt = end - beg;
    if (cnt > 0) {
        float inv = 1.0f / (float)cnt;
        float4 bb = __ldg(&((const float4*)b)[et * 32 + lane]);
        r.x = a0.x * inv + bb.x;
        r.y = a0.y * inv + bb.y;
        r.z = a0.z * inv + bb.z;
        r.w = a0.w * inv + bb.w;
    } else {
        r = make_float4(0.f, 0.f, 0.f, 0.f);
    }
    ((float4*)out)[((size_t)n * N_ET + et) * 32 + lane] = r;
}

// ---------------------------------------------------------------------------
// Round-14 schedule (unchanged):
//   s_csr    : hist_a -> (wait hist_b) scan_a -> scan_b -> scan_c -> fill [ev_fill]
//              -> (wait gemm0) gather0 -> gather1
//   stream 0 : hist_b [ev_hb] -> gemm0 [ev_g0] -> gemm1 -> gemm2
//              -> (wait fill) gather2
// ---------------------------------------------------------------------------
extern "C" void kernel_launch(void* const* d_in, const int* in_sizes, int n_in,
                              void* d_out, int out_size) {
    const float* x    = (const float*)d_in[0];
    const int*   esrc = (const int*)d_in[1];
    const int*   edst = (const int*)d_in[2];
    const float* W    = (const float*)d_in[3];
    const float* b    = (const float*)d_in[4];
    float* out = (float*)d_out;

    static cudaStream_t s_csr = nullptr;
    static cudaEvent_t ev_fork = nullptr, ev_hb = nullptr, ev_fill = nullptr;
    static cudaEvent_t ev_g0 = nullptr, ev_done = nullptr;
    if (s_csr == nullptr) {
        cudaStreamCreateWithFlags(&s_csr, cudaStreamNonBlocking);
        cudaEventCreateWithFlags(&ev_fork, cudaEventDisableTiming);
        cudaEventCreateWithFlags(&ev_hb, cudaEventDisableTiming);
        cudaEventCreateWithFlags(&ev_fill, cudaEventDisableTiming);
        cudaEventCreateWithFlags(&ev_g0, cudaEventDisableTiming);
        cudaEventCreateWithFlags(&ev_done, cudaEventDisableTiming);
    }

    const int HIST_HALF_B = (HALF_E / 4 + 255) / 256;   // 1465

    // Fork
    cudaEventRecord(ev_fork, 0);
    cudaStreamWaitEvent(s_csr, ev_fork, 0);

    // Histogram halves on both streams
    hist_kernel<<<HIST_HALF_B, 256, 0, s_csr>>>(edst, 0, HALF_E);
    hist_kernel<<<HIST_HALF_B, 256>>>(edst, HALF_E, TOTAL_E);
    cudaEventRecord(ev_hb, 0);

    // Rest of CSR build on s_csr
    cudaStreamWaitEvent(s_csr, ev_hb, 0);
    scan_a_kernel<<<SCAN_BLOCKS, 256, 0, s_csr>>>();
    scan_b_kernel<<<1, 128, 0, s_csr>>>();
    scan_c_kernel<<<(N_TOT + 255) / 256, 256, 0, s_csr>>>();
    fill_kernel<<<(TOTAL_E / 4 + 255) / 256, 256, 0, s_csr>>>(esrc, edst);
    cudaEventRecord(ev_fill, s_csr);

    // GEMMs on stream 0
    gemm_kernel<<<GEMM_BX, 256>>>(x, W, 0);
    cudaEventRecord(ev_g0, 0);
    gemm_kernel<<<GEMM_BX, 256>>>(x, W, 1);
    gemm_kernel<<<GEMM_BX, 256>>>(x, W, 2);

    // s_csr consumes etypes 0 and 1
    cudaStreamWaitEvent(s_csr, ev_g0, 0);
    gather_kernel<<<(N_NODES + 7) / 8, 256, 0, s_csr>>>(out, b, 0);
    gather_kernel<<<(N_NODES + 7) / 8, 256, 0, s_csr>>>(out, b, 1);
    cudaEventRecord(ev_done, s_csr);

    // stream 0 consumes etype 2
    cudaStreamWaitEvent(0, ev_fill, 0);
    gather_kernel<<<(N_NODES + 7) / 8, 256>>>(out, b, 2);

    // Join
    cudaStreamWaitEvent(0, ev_done, 0);
}